// round 15
// baseline (speedup 1.0000x reference)
#include <cuda_runtime.h>
#include <cstdint>
#include <cstddef>

#define NB 4
#define NS 512
#define NH 8
#define NDH 64
#define NDM 512
#define NBH 32

// ---- scratch (device globals; no allocation) ----
__device__ float g_q [NBH * NS * NDH];        // tf32-rounded
__device__ float g_k [NBH * NS * NDH];        // tf32-rounded
__device__ float g_v [NBH * NDH * NS];        // transposed [bh][d][s], tf32-rounded
__device__ float g_qr[NBH * NS * NDH];        // tf32-rounded, pre-scaled by 0.125
__device__ float g_qb[NBH * NS];              // pre-scaled by 0.125
__device__ float g_s1[(size_t)NB * NS * NH * NS];  // scores+qb+mask [b][q][h][k]
__device__ float g_p [(size_t)NB * NS * NH * NS];  // probs [b][q][h][k], tf32-rounded

__device__ __forceinline__ uint32_t f2tf(float x) {
    uint32_t r; asm("cvt.rna.tf32.f32 %0, %1;" : "=r"(r) : "f"(x)); return r;
}
__device__ __forceinline__ float f2tff(float x) { return __uint_as_float(f2tf(x)); }
__device__ __forceinline__ void mma8(float* d, const uint32_t* a, const uint32_t* b) {
    asm volatile(
        "mma.sync.aligned.m16n8k8.row.col.f32.tf32.tf32.f32 "
        "{%0,%1,%2,%3}, {%4,%5,%6,%7}, {%8,%9}, {%0,%1,%2,%3};"
        : "+f"(d[0]), "+f"(d[1]), "+f"(d[2]), "+f"(d[3])
        : "r"(a[0]), "r"(a[1]), "r"(a[2]), "r"(a[3]), "r"(b[0]), "r"(b[1]));
}
__device__ __forceinline__ void cpa16(const void* smem_dst, const void* gmem_src) {
    uint32_t s = (uint32_t)__cvta_generic_to_shared(smem_dst);
    asm volatile("cp.async.cg.shared.global [%0], [%1], 16;" :: "r"(s), "l"(gmem_src));
}
#define CP_COMMIT() asm volatile("cp.async.commit_group;")
#define CP_WAIT1()  asm volatile("cp.async.wait_group 1;")
#define CP_WAIT0()  asm volatile("cp.async.wait_group 0;")

// ========= K1: q/k/v = X @ W^T (2048x512x512), BM=128 BN=64, warp tile 32x32,
//           3-stage ring, single-sync, truncation-mode tf32; z = zbase + bz;
//           z==0 additionally computes qr = 0.125*q@Wr and qb = 0.125*q.br ===
#define K1_SMEM (20736 * 4)

__global__ void __launch_bounds__(256) k_qkv(const float* __restrict__ X,
                                             const float* __restrict__ Wq,
                                             const float* __restrict__ Wk,
                                             const float* __restrict__ Wv,
                                             const float* __restrict__ Wr,
                                             const float* __restrict__ br,
                                             int zbase) {
    extern __shared__ float dsm[];
    const int z = zbase + blockIdx.z;
    const float* __restrict__ W = (z == 0) ? Wq : (z == 1) ? Wk : Wv;
    const int tid = threadIdx.x, lane = tid & 31, w = tid >> 5;
    const int g = lane >> 2, t = lane & 3;
    const int wm = w >> 1, wn = w & 1;           // 4 x 2 warp grid, 32x32 tiles
    const int m0 = blockIdx.x * 128, n0 = blockIdx.y * 64;
    const int lr = tid >> 3, lc = (tid & 7) * 4;
    float acc[2][4][4] = {};

    auto issue = [&](int ki) {
        int st = ki % 3, kt = ki * 32;
        float* Xs = dsm + st * 4608;
        float* Ws = dsm + 13824 + st * 2304;
#pragma unroll
        for (int rr = 0; rr < 4; rr++) {
            int r = lr + rr * 32;
            cpa16(&Xs[r * 36 + lc], &X[(size_t)(m0 + r) * NDM + kt + lc]);
        }
#pragma unroll
        for (int rr = 0; rr < 2; rr++) {
            int r = lr + rr * 32;
            cpa16(&Ws[r * 36 + lc], &W[(size_t)(n0 + r) * NDM + kt + lc]);
        }
    };
    issue(0); CP_COMMIT();
    issue(1); CP_COMMIT();
    for (int ki = 0; ki < 16; ki++) {
        if (ki < 15) CP_WAIT1(); else CP_WAIT0();
        __syncthreads();
        if (ki < 14) { issue(ki + 2); CP_COMMIT(); }
        int st = ki % 3;
        const float* Xf = dsm + st * 4608;
        const float* Wf = dsm + 13824 + st * 2304;
#pragma unroll
        for (int ks = 0; ks < 4; ks++) {
            uint32_t a[2][4], bb[4][2];
#pragma unroll
            for (int mi = 0; mi < 2; mi++) {
                int r = wm * 32 + mi * 16 + g;
                a[mi][0] = __float_as_uint(Xf[r*36 + ks*8 + t]);
                a[mi][1] = __float_as_uint(Xf[(r+8)*36 + ks*8 + t]);
                a[mi][2] = __float_as_uint(Xf[r*36 + ks*8 + t + 4]);
                a[mi][3] = __float_as_uint(Xf[(r+8)*36 + ks*8 + t + 4]);
            }
#pragma unroll
            for (int ni = 0; ni < 4; ni++) {
                int c = wn * 32 + ni * 8 + g;
                bb[ni][0] = __float_as_uint(Wf[c*36 + ks*8 + t]);
                bb[ni][1] = __float_as_uint(Wf[c*36 + ks*8 + t + 4]);
            }
#pragma unroll
            for (int mi = 0; mi < 2; mi++)
#pragma unroll
                for (int ni = 0; ni < 4; ni++) mma8(acc[mi][ni], a[mi], bb[ni]);
        }
    }
    // global store of q/k/v, tf32-RN-rounded so consumers skip cvt
#pragma unroll
    for (int mi = 0; mi < 2; mi++)
#pragma unroll
        for (int ni = 0; ni < 4; ni++) {
            int m = m0 + wm*32 + mi*16 + g, n = n0 + wn*32 + ni*8 + 2*t;
            int b = m >> 9, s = m & 511, h = n >> 6, d = n & 63, bh = b*NH + h;
            if (z == 2) {
                g_v[(bh*NDH + d)  *NS + s]     = f2tff(acc[mi][ni][0]);
                g_v[(bh*NDH + d+1)*NS + s]     = f2tff(acc[mi][ni][1]);
                g_v[(bh*NDH + d)  *NS + s + 8] = f2tff(acc[mi][ni][2]);
                g_v[(bh*NDH + d+1)*NS + s + 8] = f2tff(acc[mi][ni][3]);
            } else {
                float* o = (z == 0) ? g_q : g_k;
                float* o1 = &o[((bh*NS + s)    *NDH) + d];
                float* o2 = &o[((bh*NS + s + 8)*NDH) + d];
                o1[0]=f2tff(acc[mi][ni][0]); o1[1]=f2tff(acc[mi][ni][1]);
                o2[0]=f2tff(acc[mi][ni][2]); o2[1]=f2tff(acc[mi][ni][3]);
            }
        }
    if (z != 0) return;

    // ---- fused qr/qb epilogue (this CTA holds q[m0..m0+127][head hB][0..63]) --
    float* Qs  = dsm;             // [128][68]
    float* WrT = dsm + 13824;     // [64 r][68 d]
    float* brs = dsm + 18176;
    const int hB = blockIdx.y;
    __syncthreads();
#pragma unroll
    for (int mi = 0; mi < 2; mi++)
#pragma unroll
        for (int ni = 0; ni < 4; ni++) {
            int ml = wm*32 + mi*16 + g, nl = wn*32 + ni*8 + 2*t;
            Qs[ml*68 + nl] = acc[mi][ni][0];     Qs[ml*68 + nl + 1] = acc[mi][ni][1];
            Qs[(ml+8)*68 + nl] = acc[mi][ni][2]; Qs[(ml+8)*68 + nl + 1] = acc[mi][ni][3];
        }
    for (int i = tid; i < 4096; i += 256) {
        int d = i >> 6, r = i & 63;
        WrT[r*68 + d] = Wr[i];
    }
    if (tid < 64) brs[tid] = br[tid];
    __syncthreads();

    float qacc[2][4][4] = {};
#pragma unroll
    for (int ks = 0; ks < 8; ks++) {
        uint32_t a[2][4], bb[4][2];
#pragma unroll
        for (int mi = 0; mi < 2; mi++) {
            int r = wm * 32 + mi * 16 + g;
            a[mi][0] = f2tf(Qs[r*68 + ks*8 + t]);     a[mi][1] = f2tf(Qs[(r+8)*68 + ks*8 + t]);
            a[mi][2] = f2tf(Qs[r*68 + ks*8 + t + 4]); a[mi][3] = f2tf(Qs[(r+8)*68 + ks*8 + t + 4]);
        }
#pragma unroll
        for (int ni = 0; ni < 4; ni++) {
            int c = wn * 32 + ni * 8 + g;
            bb[ni][0] = f2tf(WrT[c*68 + ks*8 + t]); bb[ni][1] = f2tf(WrT[c*68 + ks*8 + t + 4]);
        }
#pragma unroll
        for (int mi = 0; mi < 2; mi++)
#pragma unroll
            for (int ni = 0; ni < 4; ni++) mma8(qacc[mi][ni], a[mi], bb[ni]);
    }
#pragma unroll
    for (int mi = 0; mi < 2; mi++)
#pragma unroll
        for (int ni = 0; ni < 4; ni++) {
            int ml = wm*32 + mi*16 + g, col = wn*32 + ni*8 + 2*t;
            int m = m0 + ml, b = m >> 9, s = m & 511;
            float* o1 = &g_qr[(((size_t)(b*NH + hB)*NS + s)     ) * NDH + col];
            float* o2 = &g_qr[(((size_t)(b*NH + hB)*NS + (s+8)) ) * NDH + col];
            o1[0] = f2tff(qacc[mi][ni][0]) * 0.125f; o1[1] = f2tff(qacc[mi][ni][1]) * 0.125f;
            o2[0] = f2tff(qacc[mi][ni][2]) * 0.125f; o2[1] = f2tff(qacc[mi][ni][3]) * 0.125f;
        }
    // qb: 2 threads per row (128 rows)
    {
        int row = tid >> 1, half = tid & 1;
        float p = 0.f;
#pragma unroll
        for (int d = 0; d < 32; d++) p += Qs[row*68 + half*32 + d] * brs[half*32 + d];
        p += __shfl_xor_sync(0xffffffffu, p, 1);
        if (half == 0) {
            int m = m0 + row, b = m >> 9, s = m & 511;
            g_qb[(b*NH + hB)*NS + s] = p * 0.125f;
        }
    }
}

// ======= K3: s1 = 0.125*q k^T + qb + mask, -> [b][q][h][k]; cvt-free ========
__global__ void __launch_bounds__(256) k_qk(const int* __restrict__ GRAPH) {
    const int bh = blockIdx.z, b = bh >> 3, h = bh & 7;
    const float* __restrict__ Q = &g_q[(size_t)bh * NS * NDH];
    const float* __restrict__ K = &g_k[(size_t)bh * NS * NDH];
    __shared__ float As[64 * 68], Bs[64 * 68];
    __shared__ float qbs_s[64];
    const int tid = threadIdx.x, lane = tid & 31, w = tid >> 5;
    const int g = lane >> 2, t = lane & 3, wm = w >> 2, wn = w & 3;
    const int m0 = blockIdx.x * 64, n0 = blockIdx.y * 64;
#pragma unroll
    for (int rr = 0; rr < 4; rr++) {
        int r = (tid >> 4) + rr * 16, c4 = (tid & 15) * 4;
        cpa16(&As[r * 68 + c4], &Q[(m0 + r) * NDH + c4]);
        cpa16(&Bs[r * 68 + c4], &K[(n0 + r) * NDH + c4]);
    }
    CP_COMMIT();
    if (tid < 64) qbs_s[tid] = g_qb[(size_t)bh * NS + m0 + tid];
    CP_WAIT0();
    __syncthreads();
    float acc[2][2][4] = {};
#pragma unroll
    for (int ks = 0; ks < 8; ks++) {
        uint32_t a[2][4], bb[2][2];
#pragma unroll
        for (int mi = 0; mi < 2; mi++) {
            int r = wm * 32 + mi * 16 + g;
            a[mi][0] = __float_as_uint(As[r*68 + ks*8 + t]);
            a[mi][1] = __float_as_uint(As[(r+8)*68 + ks*8 + t]);
            a[mi][2] = __float_as_uint(As[r*68 + ks*8 + t + 4]);
            a[mi][3] = __float_as_uint(As[(r+8)*68 + ks*8 + t + 4]);
        }
#pragma unroll
        for (int ni = 0; ni < 2; ni++) {
            int c = wn * 16 + ni * 8 + g;
            bb[ni][0] = __float_as_uint(Bs[c*68 + ks*8 + t]);
            bb[ni][1] = __float_as_uint(Bs[c*68 + ks*8 + t + 4]);
        }
#pragma unroll
        for (int mi = 0; mi < 2; mi++)
#pragma unroll
            for (int ni = 0; ni < 2; ni++) mma8(acc[mi][ni], a[mi], bb[ni]);
    }
#pragma unroll
    for (int mi = 0; mi < 2; mi++)
#pragma unroll
        for (int ni = 0; ni < 2; ni++) {
            int m = m0 + wm*32 + mi*16 + g, n = n0 + wn*16 + ni*8 + 2*t;
            float qv1 = qbs_s[m - m0], qv2 = qbs_s[m + 8 - m0];
            int2 g1 = *(const int2*)&GRAPH[(size_t)(b*NS + m)     * NS + n];
            int2 g2 = *(const int2*)&GRAPH[(size_t)(b*NS + m + 8) * NS + n];
            float* o1 = &g_s1[((size_t)(b*NS + m)    *NH + h)*NS + n];
            float* o2 = &g_s1[((size_t)(b*NS + m + 8)*NH + h)*NS + n];
            o1[0] = acc[mi][ni][0] * 0.125f + qv1 + (1.f - (float)g1.x) * -1e9f;
            o1[1] = acc[mi][ni][1] * 0.125f + qv1 + (1.f - (float)g1.y) * -1e9f;
            o2[0] = acc[mi][ni][2] * 0.125f + qv2 + (1.f - (float)g2.x) * -1e9f;
            o2[1] = acc[mi][ni][3] * 0.125f + qv2 + (1.f - (float)g2.y) * -1e9f;
        }
}

// ===== K4: per (b,q): rel mma + premasked scores(reg) + softmax =============
// dyn smem floats: relb[2][128*68] | qrs[8*68] | red[128]
#define RELW   (128 * 68)
#define OFF_QR (2 * RELW)
#define OFF_RED (OFF_QR + 8 * 68)
#define K4_SMEM ((OFF_RED + 128) * 4)

__global__ void __launch_bounds__(256) k_relsm(const float* __restrict__ REL) {
    extern __shared__ float sm[];
    float* relb = sm;
    uint32_t* qrs = (uint32_t*)(sm + OFF_QR);
    float* red = sm + OFF_RED;   // [2][8 warps][8 h]

    const int q = blockIdx.x, b = blockIdx.y;
    const int tid = threadIdx.x, lane = tid & 31, w = tid >> 5;
    const int g = lane >> 2, t = lane & 3;

    const float* relrow = REL + (size_t)(b*NS + q) * NS * NDH;
    const float* scrow  = &g_s1[(size_t)(b*NS + q) * NH * NS];

    auto issue_rel = [&](int ch) {
        const float* src = relrow + (size_t)ch * 128 * NDH;
        float* dst = relb + (ch & 1) * RELW;
        int c4 = (tid & 15) * 4, r0 = tid >> 4;
#pragma unroll
        for (int rr = 0; rr < 8; rr++) {
            int r = r0 + rr * 16;
            cpa16(&dst[r * 68 + c4], src + (size_t)r * NDH + c4);
        }
    };
    issue_rel(0); CP_COMMIT();
    issue_rel(1); CP_COMMIT();

    // premasked scores -> registers
    float sc[16];
#pragma unroll
    for (int ch = 0; ch < 4; ch++) {
        int k0 = ch * 128 + w * 16;
#pragma unroll
        for (int j = 0; j < 4; j++) {
            int k = k0 + g + ((j >= 2) ? 8 : 0);
            int h = 2 * t + (j & 1);
            sc[ch*4+j] = scrow[(size_t)h*NS + k];
        }
    }
    for (int i = tid; i < 512; i += 256) {
        int h = i >> 6, r = i & 63;
        qrs[h * 68 + r] = __float_as_uint(g_qr[(size_t)((b*NH + h)*NS + q) * NDH + r]);
    }
    __syncthreads();
    uint32_t bf[8][2];
#pragma unroll
    for (int ks = 0; ks < 8; ks++) {
        bf[ks][0] = qrs[g*68 + ks*8 + t];
        bf[ks][1] = qrs[g*68 + ks*8 + t + 4];
    }

    for (int ch = 0; ch < 4; ch++) {
        if (ch < 3) CP_WAIT1(); else CP_WAIT0();
        __syncthreads();
        const float* buf = relb + (ch & 1) * RELW;
        float c[4] = {0,0,0,0};
        int r0 = w * 16 + g;
#pragma unroll
        for (int ks = 0; ks < 8; ks++) {
            uint32_t a[4];
            a[0] = __float_as_uint(buf[r0*68 + ks*8 + t]);
            a[1] = __float_as_uint(buf[(r0+8)*68 + ks*8 + t]);
            a[2] = __float_as_uint(buf[r0*68 + ks*8 + t + 4]);
            a[3] = __float_as_uint(buf[(r0+8)*68 + ks*8 + t + 4]);
            mma8(c, a, bf[ks]);
        }
#pragma unroll
        for (int j = 0; j < 4; j++)
            sc[ch*4+j] += c[j];
        __syncthreads();
        if (ch < 2) { issue_rel(ch + 2); CP_COMMIT(); }
    }
    // softmax: even sc index -> h=2t, odd -> h=2t+1
    float mx0 = -3e38f, mx1 = -3e38f;
#pragma unroll
    for (int i = 0; i < 16; i++) { if (i & 1) mx1 = fmaxf(mx1, sc[i]); else mx0 = fmaxf(mx0, sc[i]); }
#pragma unroll
    for (int o = 4; o < 32; o <<= 1) {
        mx0 = fmaxf(mx0, __shfl_xor_sync(0xffffffffu, mx0, o));
        mx1 = fmaxf(mx1, __shfl_xor_sync(0xffffffffu, mx1, o));
    }
    if (g == 0) { red[w*8 + 2*t] = mx0; red[w*8 + 2*t+1] = mx1; }
    __syncthreads();
    float fm0 = -3e38f, fm1 = -3e38f;
#pragma unroll
    for (int ww = 0; ww < 8; ww++) {
        fm0 = fmaxf(fm0, red[ww*8 + 2*t]); fm1 = fmaxf(fm1, red[ww*8 + 2*t+1]);
    }
    float s0 = 0.f, s1 = 0.f;
#pragma unroll
    for (int i = 0; i < 16; i++) {
        float e = __expf(sc[i] - ((i & 1) ? fm1 : fm0));
        sc[i] = e;
        if (i & 1) s1 += e; else s0 += e;
    }
#pragma unroll
    for (int o = 4; o < 32; o <<= 1) {
        s0 += __shfl_xor_sync(0xffffffffu, s0, o);
        s1 += __shfl_xor_sync(0xffffffffu, s1, o);
    }
    if (g == 0) { red[64 + w*8 + 2*t] = s0; red[64 + w*8 + 2*t+1] = s1; }
    __syncthreads();
    float ts0 = 0.f, ts1 = 0.f;
#pragma unroll
    for (int ww = 0; ww < 8; ww++) { ts0 += red[64 + ww*8 + 2*t]; ts1 += red[64 + ww*8 + 2*t+1]; }
    float r0i = 1.f / ts0, r1i = 1.f / ts1;

    // stage probs [h][k] into relb (tf32-RN-rounded so k_pv skips cvt)
    float* pbuf = relb;
    __syncthreads();
#pragma unroll
    for (int ch = 0; ch < 4; ch++) {
        int k0 = ch * 128 + w * 16;
#pragma unroll
        for (int j = 0; j < 4; j++) {
            int k = k0 + g + ((j >= 2) ? 8 : 0);
            int h = 2 * t + (j & 1);
            pbuf[h * NS + k] = f2tff(sc[ch*4+j] * ((j & 1) ? r1i : r0i));
        }
    }
    __syncthreads();
    float* pout = &g_p[(size_t)(b*NS + q) * NH * NS];
    for (int i = tid; i < 1024; i += 256)
        *(float4*)&pout[i * 4] = *(const float4*)&pbuf[i * 4];
}

// ========= K5: out = probs @ v per (b,h), BM=64, 3-stage ring, cvt-free =====
#define K5_SMEM (3 * 2 * 2304 * 4)

__global__ void __launch_bounds__(256) k_pv(float* __restrict__ OUT) {
    extern __shared__ float dsm[];
    const int bh = blockIdx.z, b = bh >> 3, h = bh & 7;
    const float* __restrict__ VT = &g_v[(size_t)bh * NDH * NS];
    const int tid = threadIdx.x, lane = tid & 31, w = tid >> 5;
    const int g = lane >> 2, t = lane & 3, wm = w >> 2, wn = w & 3;
    const int m0 = blockIdx.x * 64;
    const int lr = tid >> 3, lc = (tid & 7) * 4;
    float acc[2][2][4] = {};

    auto issue = [&](int ki) {
        int st = ki % 3, kt = ki * 32;
        float* As = dsm + st * 2304;
        float* Bs = dsm + 6912 + st * 2304;
#pragma unroll
        for (int rr = 0; rr < 2; rr++) {
            int r = lr + rr * 32;
            cpa16(&As[r * 36 + lc], &g_p[((size_t)(b*NS + m0 + r)*NH + h)*NS + kt + lc]);
            cpa16(&Bs[r * 36 + lc], &VT[(size_t)r * NS + kt + lc]);
        }
    };
    issue(0); CP_COMMIT();
    issue(1); CP_COMMIT();
    for (int ki = 0; ki < 16; ki++) {
        if (ki < 15) CP_WAIT1(); else CP_WAIT0();
        __syncthreads();
        if (ki < 14) { issue(ki + 2); CP_COMMIT(); }
        int st = ki % 3;
        const float* Af = dsm + st * 2304;
        const float* Bf = dsm + 6912 + st * 2304;
#pragma unroll
        for (int ks = 0; ks < 4; ks++) {
            uint32_t a[2][4], bb[2][2];
#pragma unroll
            for (int mi = 0; mi < 2; mi++) {
                int r = wm * 32 + mi * 16 + g;
                a[mi][0] = __float_as_uint(Af[r*36 + ks*8 + t]);
                a[mi][1] = __float_as_uint(Af[(r+8)*36 + ks*8 + t]);
                a[mi][2] = __float_as_uint(Af[r*36 + ks*8 + t + 4]);
                a[mi][3] = __float_as_uint(Af[(r+8)*36 + ks*8 + t + 4]);
            }
#pragma unroll
            for (int ni = 0; ni < 2; ni++) {
                int c = wn * 16 + ni * 8 + g;
                bb[ni][0] = __float_as_uint(Bf[c*36 + ks*8 + t]);
                bb[ni][1] = __float_as_uint(Bf[c*36 + ks*8 + t + 4]);
            }
#pragma unroll
            for (int mi = 0; mi < 2; mi++)
#pragma unroll
                for (int ni = 0; ni < 2; ni++) mma8(acc[mi][ni], a[mi], bb[ni]);
        }
    }
#pragma unroll
    for (int mi = 0; mi < 2; mi++)
#pragma unroll
        for (int ni = 0; ni < 2; ni++) {
            int m = m0 + wm*32 + mi*16 + g, n = wn*16 + ni*8 + 2*t;
            float* o1 = &OUT[(size_t)(b*NS + m)    *NDM + h*NDH + n];
            float* o2 = &OUT[(size_t)(b*NS + m + 8)*NDM + h*NDH + n];
            o1[0]=acc[mi][ni][0]; o1[1]=acc[mi][ni][1];
            o2[0]=acc[mi][ni][2]; o2[1]=acc[mi][ni][3];
        }
}

extern "C" void kernel_launch(void* const* d_in, const int* in_sizes, int n_in,
                              void* d_out, int out_size) {
    const float* X     = (const float*)d_in[0];
    const int*   GRAPH = (const int*)  d_in[1];
    const float* REL   = (const float*)d_in[2];
    const float* Wq    = (const float*)d_in[3];
    const float* Wk    = (const float*)d_in[4];
    const float* Wv    = (const float*)d_in[5];
    const float* Wr    = (const float*)d_in[6];
    const float* br    = (const float*)d_in[7];
    float* OUT = (float*)d_out;

    static cudaStream_t s2 = nullptr;
    static cudaEvent_t e0 = nullptr, e1 = nullptr;
    if (!s2) {
        cudaFuncSetAttribute(k_qkv,   cudaFuncAttributeMaxDynamicSharedMemorySize, K1_SMEM);
        cudaFuncSetAttribute(k_relsm, cudaFuncAttributeMaxDynamicSharedMemorySize, K4_SMEM);
        cudaFuncSetAttribute(k_pv,    cudaFuncAttributeMaxDynamicSharedMemorySize, K5_SMEM);
        cudaStreamCreateWithFlags(&s2, cudaStreamNonBlocking);
        cudaEventCreateWithFlags(&e0, cudaEventDisableTiming);
        cudaEventCreateWithFlags(&e1, cudaEventDisableTiming);
    }

    // q + k (main), then fork: v on side stream while qk runs on main
    k_qkv  <<<dim3(16, 8, 2), 256, K1_SMEM>>>(X, Wq, Wk, Wv, Wr, br, 0);
    cudaEventRecord(e0, 0);
    cudaStreamWaitEvent(s2, e0, 0);
    k_qkv  <<<dim3(16, 8, 1), 256, K1_SMEM, s2>>>(X, Wq, Wk, Wv, Wr, br, 2);
    cudaEventRecord(e1, s2);

    k_qk   <<<dim3(8, 8, 32), 256>>>(GRAPH);
    k_relsm<<<dim3(512, 4), 256, K4_SMEM>>>(REL);
    cudaStreamWaitEvent(0, e1, 0);
    k_pv   <<<dim3(8, 1, 32), 256, K5_SMEM>>>(OUT);
}

// round 16
// speedup vs baseline: 1.0002x; 1.0002x over previous
#include <cuda_runtime.h>
#include <cstdint>
#include <cstddef>

#define NB 4
#define NS 512
#define NH 8
#define NDH 64
#define NDM 512
#define NBH 32

// ---- scratch (device globals; no allocation) ----
__device__ float g_q [NBH * NS * NDH];        // tf32-rounded
__device__ float g_k [NBH * NS * NDH];        // tf32-rounded
__device__ float g_v [NBH * NDH * NS];        // transposed [bh][d][s], tf32-rounded
__device__ float g_qr[NBH * NS * NDH];        // tf32-rounded, pre-scaled by 0.125
__device__ float g_qb[NBH * NS];              // pre-scaled by 0.125
__device__ float g_s1[(size_t)NB * NS * NH * NS];  // scores+qb+mask [b][q][h][k]
__device__ float g_p [(size_t)NB * NS * NH * NS];  // probs [b][q][h][k], tf32-rounded

__device__ __forceinline__ uint32_t f2tf(float x) {
    uint32_t r; asm("cvt.rna.tf32.f32 %0, %1;" : "=r"(r) : "f"(x)); return r;
}
__device__ __forceinline__ float f2tff(float x) { return __uint_as_float(f2tf(x)); }
__device__ __forceinline__ void mma8(float* d, const uint32_t* a, const uint32_t* b) {
    asm volatile(
        "mma.sync.aligned.m16n8k8.row.col.f32.tf32.tf32.f32 "
        "{%0,%1,%2,%3}, {%4,%5,%6,%7}, {%8,%9}, {%0,%1,%2,%3};"
        : "+f"(d[0]), "+f"(d[1]), "+f"(d[2]), "+f"(d[3])
        : "r"(a[0]), "r"(a[1]), "r"(a[2]), "r"(a[3]), "r"(b[0]), "r"(b[1]));
}
__device__ __forceinline__ void cpa16(const void* smem_dst, const void* gmem_src) {
    uint32_t s = (uint32_t)__cvta_generic_to_shared(smem_dst);
    asm volatile("cp.async.cg.shared.global [%0], [%1], 16;" :: "r"(s), "l"(gmem_src));
}
#define CP_COMMIT() asm volatile("cp.async.commit_group;")
#define CP_WAIT1()  asm volatile("cp.async.wait_group 1;")
#define CP_WAIT0()  asm volatile("cp.async.wait_group 0;")

// ========= K1: q/k/v = X @ W^T (2048x512x512), BM=128 BN=64, warp tile 32x32,
//           3-stage ring, single-sync, truncation-mode tf32;
//           z==0 additionally computes qr = 0.125*q@Wr and qb = 0.125*q.br ===
#define K1_SMEM (20736 * 4)

__global__ void __launch_bounds__(256) k_qkv(const float* __restrict__ X,
                                             const float* __restrict__ Wq,
                                             const float* __restrict__ Wk,
                                             const float* __restrict__ Wv,
                                             const float* __restrict__ Wr,
                                             const float* __restrict__ br) {
    extern __shared__ float dsm[];
    const int z = blockIdx.z;
    const float* __restrict__ W = (z == 0) ? Wq : (z == 1) ? Wk : Wv;
    const int tid = threadIdx.x, lane = tid & 31, w = tid >> 5;
    const int g = lane >> 2, t = lane & 3;
    const int wm = w >> 1, wn = w & 1;           // 4 x 2 warp grid, 32x32 tiles
    const int m0 = blockIdx.x * 128, n0 = blockIdx.y * 64;
    const int lr = tid >> 3, lc = (tid & 7) * 4;
    float acc[2][4][4] = {};

    auto issue = [&](int ki) {
        int st = ki % 3, kt = ki * 32;
        float* Xs = dsm + st * 4608;
        float* Ws = dsm + 13824 + st * 2304;
#pragma unroll
        for (int rr = 0; rr < 4; rr++) {
            int r = lr + rr * 32;
            cpa16(&Xs[r * 36 + lc], &X[(size_t)(m0 + r) * NDM + kt + lc]);
        }
#pragma unroll
        for (int rr = 0; rr < 2; rr++) {
            int r = lr + rr * 32;
            cpa16(&Ws[r * 36 + lc], &W[(size_t)(n0 + r) * NDM + kt + lc]);
        }
    };
    issue(0); CP_COMMIT();
    issue(1); CP_COMMIT();
    for (int ki = 0; ki < 16; ki++) {
        if (ki < 15) CP_WAIT1(); else CP_WAIT0();
        __syncthreads();
        if (ki < 14) { issue(ki + 2); CP_COMMIT(); }
        int st = ki % 3;
        const float* Xf = dsm + st * 4608;
        const float* Wf = dsm + 13824 + st * 2304;
#pragma unroll
        for (int ks = 0; ks < 4; ks++) {
            uint32_t a[2][4], bb[4][2];
#pragma unroll
            for (int mi = 0; mi < 2; mi++) {
                int r = wm * 32 + mi * 16 + g;
                a[mi][0] = __float_as_uint(Xf[r*36 + ks*8 + t]);
                a[mi][1] = __float_as_uint(Xf[(r+8)*36 + ks*8 + t]);
                a[mi][2] = __float_as_uint(Xf[r*36 + ks*8 + t + 4]);
                a[mi][3] = __float_as_uint(Xf[(r+8)*36 + ks*8 + t + 4]);
            }
#pragma unroll
            for (int ni = 0; ni < 4; ni++) {
                int c = wn * 32 + ni * 8 + g;
                bb[ni][0] = __float_as_uint(Wf[c*36 + ks*8 + t]);
                bb[ni][1] = __float_as_uint(Wf[c*36 + ks*8 + t + 4]);
            }
#pragma unroll
            for (int mi = 0; mi < 2; mi++)
#pragma unroll
                for (int ni = 0; ni < 4; ni++) mma8(acc[mi][ni], a[mi], bb[ni]);
        }
    }
    // global store of q/k/v, tf32-RN-rounded so consumers skip cvt
#pragma unroll
    for (int mi = 0; mi < 2; mi++)
#pragma unroll
        for (int ni = 0; ni < 4; ni++) {
            int m = m0 + wm*32 + mi*16 + g, n = n0 + wn*32 + ni*8 + 2*t;
            int b = m >> 9, s = m & 511, h = n >> 6, d = n & 63, bh = b*NH + h;
            if (z == 2) {
                g_v[(bh*NDH + d)  *NS + s]     = f2tff(acc[mi][ni][0]);
                g_v[(bh*NDH + d+1)*NS + s]     = f2tff(acc[mi][ni][1]);
                g_v[(bh*NDH + d)  *NS + s + 8] = f2tff(acc[mi][ni][2]);
                g_v[(bh*NDH + d+1)*NS + s + 8] = f2tff(acc[mi][ni][3]);
            } else {
                float* o = (z == 0) ? g_q : g_k;
                float* o1 = &o[((bh*NS + s)    *NDH) + d];
                float* o2 = &o[((bh*NS + s + 8)*NDH) + d];
                o1[0]=f2tff(acc[mi][ni][0]); o1[1]=f2tff(acc[mi][ni][1]);
                o2[0]=f2tff(acc[mi][ni][2]); o2[1]=f2tff(acc[mi][ni][3]);
            }
        }
    if (z != 0) return;

    // ---- fused qr/qb epilogue (this CTA holds q[m0..m0+127][head hB][0..63]) --
    float* Qs  = dsm;             // [128][68]
    float* WrT = dsm + 13824;     // [64 r][68 d]
    float* brs = dsm + 18176;
    const int hB = blockIdx.y;
    __syncthreads();
#pragma unroll
    for (int mi = 0; mi < 2; mi++)
#pragma unroll
        for (int ni = 0; ni < 4; ni++) {
            int ml = wm*32 + mi*16 + g, nl = wn*32 + ni*8 + 2*t;
            Qs[ml*68 + nl] = acc[mi][ni][0];     Qs[ml*68 + nl + 1] = acc[mi][ni][1];
            Qs[(ml+8)*68 + nl] = acc[mi][ni][2]; Qs[(ml+8)*68 + nl + 1] = acc[mi][ni][3];
        }
    for (int i = tid; i < 4096; i += 256) {
        int d = i >> 6, r = i & 63;
        WrT[r*68 + d] = Wr[i];
    }
    if (tid < 64) brs[tid] = br[tid];
    __syncthreads();

    float qacc[2][4][4] = {};
#pragma unroll
    for (int ks = 0; ks < 8; ks++) {
        uint32_t a[2][4], bb[4][2];
#pragma unroll
        for (int mi = 0; mi < 2; mi++) {
            int r = wm * 32 + mi * 16 + g;
            a[mi][0] = f2tf(Qs[r*68 + ks*8 + t]);     a[mi][1] = f2tf(Qs[(r+8)*68 + ks*8 + t]);
            a[mi][2] = f2tf(Qs[r*68 + ks*8 + t + 4]); a[mi][3] = f2tf(Qs[(r+8)*68 + ks*8 + t + 4]);
        }
#pragma unroll
        for (int ni = 0; ni < 4; ni++) {
            int c = wn * 32 + ni * 8 + g;
            bb[ni][0] = f2tf(WrT[c*68 + ks*8 + t]); bb[ni][1] = f2tf(WrT[c*68 + ks*8 + t + 4]);
        }
#pragma unroll
        for (int mi = 0; mi < 2; mi++)
#pragma unroll
            for (int ni = 0; ni < 4; ni++) mma8(qacc[mi][ni], a[mi], bb[ni]);
    }
#pragma unroll
    for (int mi = 0; mi < 2; mi++)
#pragma unroll
        for (int ni = 0; ni < 4; ni++) {
            int ml = wm*32 + mi*16 + g, col = wn*32 + ni*8 + 2*t;
            int m = m0 + ml, b = m >> 9, s = m & 511;
            float* o1 = &g_qr[(((size_t)(b*NH + hB)*NS + s)     ) * NDH + col];
            float* o2 = &g_qr[(((size_t)(b*NH + hB)*NS + (s+8)) ) * NDH + col];
            o1[0] = f2tff(qacc[mi][ni][0]) * 0.125f; o1[1] = f2tff(qacc[mi][ni][1]) * 0.125f;
            o2[0] = f2tff(qacc[mi][ni][2]) * 0.125f; o2[1] = f2tff(qacc[mi][ni][3]) * 0.125f;
        }
    // qb: 2 threads per row (128 rows)
    {
        int row = tid >> 1, half = tid & 1;
        float p = 0.f;
#pragma unroll
        for (int d = 0; d < 32; d++) p += Qs[row*68 + half*32 + d] * brs[half*32 + d];
        p += __shfl_xor_sync(0xffffffffu, p, 1);
        if (half == 0) {
            int m = m0 + row, b = m >> 9, s = m & 511;
            g_qb[(b*NH + hB)*NS + s] = p * 0.125f;
        }
    }
}

// ======= K3: s1 = 0.125*q k^T + qb + mask, -> [b][q][h][k]; cvt-free ========
__global__ void __launch_bounds__(256) k_qk(const int* __restrict__ GRAPH) {
    const int bh = blockIdx.z, b = bh >> 3, h = bh & 7;
    const float* __restrict__ Q = &g_q[(size_t)bh * NS * NDH];
    const float* __restrict__ K = &g_k[(size_t)bh * NS * NDH];
    __shared__ float As[64 * 68], Bs[64 * 68];
    __shared__ float qbs_s[64];
    const int tid = threadIdx.x, lane = tid & 31, w = tid >> 5;
    const int g = lane >> 2, t = lane & 3, wm = w >> 2, wn = w & 3;
    const int m0 = blockIdx.x * 64, n0 = blockIdx.y * 64;
#pragma unroll
    for (int rr = 0; rr < 4; rr++) {
        int r = (tid >> 4) + rr * 16, c4 = (tid & 15) * 4;
        cpa16(&As[r * 68 + c4], &Q[(m0 + r) * NDH + c4]);
        cpa16(&Bs[r * 68 + c4], &K[(n0 + r) * NDH + c4]);
    }
    CP_COMMIT();
    if (tid < 64) qbs_s[tid] = g_qb[(size_t)bh * NS + m0 + tid];
    CP_WAIT0();
    __syncthreads();
    float acc[2][2][4] = {};
#pragma unroll
    for (int ks = 0; ks < 8; ks++) {
        uint32_t a[2][4], bb[2][2];
#pragma unroll
        for (int mi = 0; mi < 2; mi++) {
            int r = wm * 32 + mi * 16 + g;
            a[mi][0] = __float_as_uint(As[r*68 + ks*8 + t]);
            a[mi][1] = __float_as_uint(As[(r+8)*68 + ks*8 + t]);
            a[mi][2] = __float_as_uint(As[r*68 + ks*8 + t + 4]);
            a[mi][3] = __float_as_uint(As[(r+8)*68 + ks*8 + t + 4]);
        }
#pragma unroll
        for (int ni = 0; ni < 2; ni++) {
            int c = wn * 16 + ni * 8 + g;
            bb[ni][0] = __float_as_uint(Bs[c*68 + ks*8 + t]);
            bb[ni][1] = __float_as_uint(Bs[c*68 + ks*8 + t + 4]);
        }
#pragma unroll
        for (int mi = 0; mi < 2; mi++)
#pragma unroll
            for (int ni = 0; ni < 2; ni++) mma8(acc[mi][ni], a[mi], bb[ni]);
    }
#pragma unroll
    for (int mi = 0; mi < 2; mi++)
#pragma unroll
        for (int ni = 0; ni < 2; ni++) {
            int m = m0 + wm*32 + mi*16 + g, n = n0 + wn*16 + ni*8 + 2*t;
            float qv1 = qbs_s[m - m0], qv2 = qbs_s[m + 8 - m0];
            int2 g1 = *(const int2*)&GRAPH[(size_t)(b*NS + m)     * NS + n];
            int2 g2 = *(const int2*)&GRAPH[(size_t)(b*NS + m + 8) * NS + n];
            float* o1 = &g_s1[((size_t)(b*NS + m)    *NH + h)*NS + n];
            float* o2 = &g_s1[((size_t)(b*NS + m + 8)*NH + h)*NS + n];
            o1[0] = acc[mi][ni][0] * 0.125f + qv1 + (1.f - (float)g1.x) * -1e9f;
            o1[1] = acc[mi][ni][1] * 0.125f + qv1 + (1.f - (float)g1.y) * -1e9f;
            o2[0] = acc[mi][ni][2] * 0.125f + qv2 + (1.f - (float)g2.x) * -1e9f;
            o2[1] = acc[mi][ni][3] * 0.125f + qv2 + (1.f - (float)g2.y) * -1e9f;
        }
}

// ===== K4: per (b,q): rel mma + premasked scores(reg) + softmax =============
// dyn smem floats: relb[2][128*68] | qrs[8*68] | red[128]
#define RELW   (128 * 68)
#define OFF_QR (2 * RELW)
#define OFF_RED (OFF_QR + 8 * 68)
#define K4_SMEM ((OFF_RED + 128) * 4)

__global__ void __launch_bounds__(256) k_relsm(const float* __restrict__ REL) {
    extern __shared__ float sm[];
    float* relb = sm;
    uint32_t* qrs = (uint32_t*)(sm + OFF_QR);
    float* red = sm + OFF_RED;   // [2][8 warps][8 h]

    const int q = blockIdx.x, b = blockIdx.y;
    const int tid = threadIdx.x, lane = tid & 31, w = tid >> 5;
    const int g = lane >> 2, t = lane & 3;

    const float* relrow = REL + (size_t)(b*NS + q) * NS * NDH;
    const float* scrow  = &g_s1[(size_t)(b*NS + q) * NH * NS];

    auto issue_rel = [&](int ch) {
        const float* src = relrow + (size_t)ch * 128 * NDH;
        float* dst = relb + (ch & 1) * RELW;
        int c4 = (tid & 15) * 4, r0 = tid >> 4;
#pragma unroll
        for (int rr = 0; rr < 8; rr++) {
            int r = r0 + rr * 16;
            cpa16(&dst[r * 68 + c4], src + (size_t)r * NDH + c4);
        }
    };
    issue_rel(0); CP_COMMIT();
    issue_rel(1); CP_COMMIT();

    // premasked scores -> registers
    float sc[16];
#pragma unroll
    for (int ch = 0; ch < 4; ch++) {
        int k0 = ch * 128 + w * 16;
#pragma unroll
        for (int j = 0; j < 4; j++) {
            int k = k0 + g + ((j >= 2) ? 8 : 0);
            int h = 2 * t + (j & 1);
            sc[ch*4+j] = scrow[(size_t)h*NS + k];
        }
    }
    for (int i = tid; i < 512; i += 256) {
        int h = i >> 6, r = i & 63;
        qrs[h * 68 + r] = __float_as_uint(g_qr[(size_t)((b*NH + h)*NS + q) * NDH + r]);
    }
    __syncthreads();
    uint32_t bf[8][2];
#pragma unroll
    for (int ks = 0; ks < 8; ks++) {
        bf[ks][0] = qrs[g*68 + ks*8 + t];
        bf[ks][1] = qrs[g*68 + ks*8 + t + 4];
    }

    for (int ch = 0; ch < 4; ch++) {
        if (ch < 3) CP_WAIT1(); else CP_WAIT0();
        __syncthreads();
        const float* buf = relb + (ch & 1) * RELW;
        float c[4] = {0,0,0,0};
        int r0 = w * 16 + g;
#pragma unroll
        for (int ks = 0; ks < 8; ks++) {
            uint32_t a[4];
            a[0] = __float_as_uint(buf[r0*68 + ks*8 + t]);
            a[1] = __float_as_uint(buf[(r0+8)*68 + ks*8 + t]);
            a[2] = __float_as_uint(buf[r0*68 + ks*8 + t + 4]);
            a[3] = __float_as_uint(buf[(r0+8)*68 + ks*8 + t + 4]);
            mma8(c, a, bf[ks]);
        }
#pragma unroll
        for (int j = 0; j < 4; j++)
            sc[ch*4+j] += c[j];
        __syncthreads();
        if (ch < 2) { issue_rel(ch + 2); CP_COMMIT(); }
    }
    // softmax: even sc index -> h=2t, odd -> h=2t+1
    float mx0 = -3e38f, mx1 = -3e38f;
#pragma unroll
    for (int i = 0; i < 16; i++) { if (i & 1) mx1 = fmaxf(mx1, sc[i]); else mx0 = fmaxf(mx0, sc[i]); }
#pragma unroll
    for (int o = 4; o < 32; o <<= 1) {
        mx0 = fmaxf(mx0, __shfl_xor_sync(0xffffffffu, mx0, o));
        mx1 = fmaxf(mx1, __shfl_xor_sync(0xffffffffu, mx1, o));
    }
    if (g == 0) { red[w*8 + 2*t] = mx0; red[w*8 + 2*t+1] = mx1; }
    __syncthreads();
    float fm0 = -3e38f, fm1 = -3e38f;
#pragma unroll
    for (int ww = 0; ww < 8; ww++) {
        fm0 = fmaxf(fm0, red[ww*8 + 2*t]); fm1 = fmaxf(fm1, red[ww*8 + 2*t+1]);
    }
    float s0 = 0.f, s1 = 0.f;
#pragma unroll
    for (int i = 0; i < 16; i++) {
        float e = __expf(sc[i] - ((i & 1) ? fm1 : fm0));
        sc[i] = e;
        if (i & 1) s1 += e; else s0 += e;
    }
#pragma unroll
    for (int o = 4; o < 32; o <<= 1) {
        s0 += __shfl_xor_sync(0xffffffffu, s0, o);
        s1 += __shfl_xor_sync(0xffffffffu, s1, o);
    }
    if (g == 0) { red[64 + w*8 + 2*t] = s0; red[64 + w*8 + 2*t+1] = s1; }
    __syncthreads();
    float ts0 = 0.f, ts1 = 0.f;
#pragma unroll
    for (int ww = 0; ww < 8; ww++) { ts0 += red[64 + ww*8 + 2*t]; ts1 += red[64 + ww*8 + 2*t+1]; }
    float r0i = 1.f / ts0, r1i = 1.f / ts1;

    // stage probs [h][k] into relb (tf32-RN-rounded so k_pv skips cvt)
    float* pbuf = relb;
    __syncthreads();
#pragma unroll
    for (int ch = 0; ch < 4; ch++) {
        int k0 = ch * 128 + w * 16;
#pragma unroll
        for (int j = 0; j < 4; j++) {
            int k = k0 + g + ((j >= 2) ? 8 : 0);
            int h = 2 * t + (j & 1);
            pbuf[h * NS + k] = f2tff(sc[ch*4+j] * ((j & 1) ? r1i : r0i));
        }
    }
    __syncthreads();
    float* pout = &g_p[(size_t)(b*NS + q) * NH * NS];
    for (int i = tid; i < 1024; i += 256)
        *(float4*)&pout[i * 4] = *(const float4*)&pbuf[i * 4];
}

// ========= K5: out = probs @ v per (b,h), BM=64, 3-stage ring, cvt-free =====
#define K5_SMEM (3 * 2 * 2304 * 4)

__global__ void __launch_bounds__(256) k_pv(float* __restrict__ OUT) {
    extern __shared__ float dsm[];
    const int bh = blockIdx.z, b = bh >> 3, h = bh & 7;
    const float* __restrict__ VT = &g_v[(size_t)bh * NDH * NS];
    const int tid = threadIdx.x, lane = tid & 31, w = tid >> 5;
    const int g = lane >> 2, t = lane & 3, wm = w >> 2, wn = w & 3;
    const int m0 = blockIdx.x * 64;
    const int lr = tid >> 3, lc = (tid & 7) * 4;
    float acc[2][2][4] = {};

    auto issue = [&](int ki) {
        int st = ki % 3, kt = ki * 32;
        float* As = dsm + st * 2304;
        float* Bs = dsm + 6912 + st * 2304;
#pragma unroll
        for (int rr = 0; rr < 2; rr++) {
            int r = lr + rr * 32;
            cpa16(&As[r * 36 + lc], &g_p[((size_t)(b*NS + m0 + r)*NH + h)*NS + kt + lc]);
            cpa16(&Bs[r * 36 + lc], &VT[(size_t)r * NS + kt + lc]);
        }
    };
    issue(0); CP_COMMIT();
    issue(1); CP_COMMIT();
    for (int ki = 0; ki < 16; ki++) {
        if (ki < 15) CP_WAIT1(); else CP_WAIT0();
        __syncthreads();
        if (ki < 14) { issue(ki + 2); CP_COMMIT(); }
        int st = ki % 3;
        const float* Af = dsm + st * 2304;
        const float* Bf = dsm + 6912 + st * 2304;
#pragma unroll
        for (int ks = 0; ks < 4; ks++) {
            uint32_t a[2][4], bb[2][2];
#pragma unroll
            for (int mi = 0; mi < 2; mi++) {
                int r = wm * 32 + mi * 16 + g;
                a[mi][0] = __float_as_uint(Af[r*36 + ks*8 + t]);
                a[mi][1] = __float_as_uint(Af[(r+8)*36 + ks*8 + t]);
                a[mi][2] = __float_as_uint(Af[r*36 + ks*8 + t + 4]);
                a[mi][3] = __float_as_uint(Af[(r+8)*36 + ks*8 + t + 4]);
            }
#pragma unroll
            for (int ni = 0; ni < 2; ni++) {
                int c = wn * 16 + ni * 8 + g;
                bb[ni][0] = __float_as_uint(Bf[c*36 + ks*8 + t]);
                bb[ni][1] = __float_as_uint(Bf[c*36 + ks*8 + t + 4]);
            }
#pragma unroll
            for (int mi = 0; mi < 2; mi++)
#pragma unroll
                for (int ni = 0; ni < 2; ni++) mma8(acc[mi][ni], a[mi], bb[ni]);
        }
    }
#pragma unroll
    for (int mi = 0; mi < 2; mi++)
#pragma unroll
        for (int ni = 0; ni < 2; ni++) {
            int m = m0 + wm*32 + mi*16 + g, n = wn*16 + ni*8 + 2*t;
            float* o1 = &OUT[(size_t)(b*NS + m)    *NDM + h*NDH + n];
            float* o2 = &OUT[(size_t)(b*NS + m + 8)*NDM + h*NDH + n];
            o1[0]=acc[mi][ni][0]; o1[1]=acc[mi][ni][1];
            o2[0]=acc[mi][ni][2]; o2[1]=acc[mi][ni][3];
        }
}

extern "C" void kernel_launch(void* const* d_in, const int* in_sizes, int n_in,
                              void* d_out, int out_size) {
    const float* X     = (const float*)d_in[0];
    const int*   GRAPH = (const int*)  d_in[1];
    const float* REL   = (const float*)d_in[2];
    const float* Wq    = (const float*)d_in[3];
    const float* Wk    = (const float*)d_in[4];
    const float* Wv    = (const float*)d_in[5];
    const float* Wr    = (const float*)d_in[6];
    const float* br    = (const float*)d_in[7];
    float* OUT = (float*)d_out;

    static bool attr_set = false;
    if (!attr_set) {
        cudaFuncSetAttribute(k_qkv,   cudaFuncAttributeMaxDynamicSharedMemorySize, K1_SMEM);
        cudaFuncSetAttribute(k_relsm, cudaFuncAttributeMaxDynamicSharedMemorySize, K4_SMEM);
        cudaFuncSetAttribute(k_pv,    cudaFuncAttributeMaxDynamicSharedMemorySize, K5_SMEM);
        attr_set = true;
    }

    k_qkv  <<<dim3(16, 8, 3), 256, K1_SMEM>>>(X, Wq, Wk, Wv, Wr, br);
    k_qk   <<<dim3(8, 8, 32), 256>>>(GRAPH);
    k_relsm<<<dim3(512, 4), 256, K4_SMEM>>>(REL);
    k_pv   <<<dim3(8, 1, 32), 256, K5_SMEM>>>(OUT);
}